// round 4
// baseline (speedup 1.0000x reference)
#include <cuda_runtime.h>
#include <cuda_bf16.h>
#include <cstdint>
#include <cstddef>

// Shapes (fixed for this problem)
#define BW 64
#define BO 64
#define TW 32
#define TO 36
#define DD 512

// smem row strides (floats). 516 = 512 + 4 pad: keeps float4 alignment and
// spreads row-to-row bank-group offsets (4*516 % 32 == 16).
#define SW 516
#define SU 516

// dynamic smem layout (float offsets)
#define OFF_US   (32 * SW)                 // 16512 : u tile [36][516] (later o tile [36][512])
#define OFF_PART (OFF_US + 36 * SU)        // 35088 : k-split partials 4*[36][32]; att_ts [36][36] overlays it
#define OFF_LP   (OFF_PART + 4 * 1152)     // 39696 : logits partials [2][32]
#define SMEM_FLOATS (OFF_LP + 64)
#define SMEM_BYTES  (SMEM_FLOATS * 4)      // 159040 B  (<= 227KB limit)

// logits scratch [w][t][b]
__device__ float g_logits[BW * TW * BO];

__device__ __forceinline__ void cpa16(float* s, const float* g) {
    uint32_t sa = (uint32_t)__cvta_generic_to_shared(s);
    asm volatile("cp.async.cg.shared.global [%0], [%1], 16;" :: "r"(sa), "l"(g));
}
__device__ __forceinline__ void cp_commit() { asm volatile("cp.async.commit_group;"); }
__device__ __forceinline__ void cp_wait0()  { asm volatile("cp.async.wait_group 0;"); }

__global__ void __launch_bounds__(512, 1)
cap_main(const float* __restrict__ o_g, const float* __restrict__ u_g,
         const float* __restrict__ w_g,
         float* __restrict__ att_out, float* __restrict__ avo_out)
{
    extern __shared__ float sm[];
    float* w_s    = sm;              // [32][SW], natural [t][k]
    float* u_s    = sm + OFF_US;     // [36][SU] (stage1) / o tile [36][512] (stage2)
    float* part   = sm + OFF_PART;   // [4][36][32]
    float* att_ts = part;            // [36][36] (o-major, padded to 36) overlays part (safe: read-all->sync->write)
    float* lp     = sm + OFF_LP;     // [2][32]

    const int b    = blockIdx.x;     // Bo index
    const int wb   = blockIdx.y;     // Bw index
    const int tid  = threadIdx.x;
    const int lane = tid & 31;
    const int warp = tid >> 5;

    const float* wg = w_g + (size_t)wb * TW * DD;
    const float* ug = u_g + (size_t)b  * TO * DD;
    const float* og = o_g + (size_t)b  * TO * DD;

    // ---- load w and u tiles (coalesced float4 via cp.async) ----
    for (int i = tid; i < TW * DD / 4; i += 512) {
        int t = i >> 7, k4 = i & 127;
        cpa16(&w_s[t * SW + k4 * 4], wg + t * DD + k4 * 4);
    }
    for (int i = tid; i < TO * DD / 4; i += 512) {
        int r = i >> 7, k4 = i & 127;
        cpa16(&u_s[r * SU + k4 * 4], ug + r * DD + k4 * 4);
    }
    cp_commit();
    cp_wait0();
    __syncthreads();

    // ---- stage 1: scores(32x36) = w(32x512) . u^T, 4-way K-split ----
    if (tid < 288) {
        const int g    = tid / 72;
        const int id72 = tid % 72;
        const int oc   = id72 >> 3;      // 0..8  (oc-major within warps -> few b-conflicts)
        const int tr   = id72 & 7;       // 0..7
        const int t0 = tr * 4, o0 = oc * 4;
        const float* wp = w_s + t0 * SW + g * 128;
        const float* up = u_s + o0 * SU + g * 128;

        float acc[4][4];
        #pragma unroll
        for (int i = 0; i < 4; i++)
            #pragma unroll
            for (int j = 0; j < 4; j++) acc[i][j] = 0.f;

        #pragma unroll 2
        for (int k4 = 0; k4 < 32; k4++) {
            const int kk = k4 * 4;
            float4 aq[4], bq[4];
            #pragma unroll
            for (int i = 0; i < 4; i++) aq[i] = *(const float4*)(wp + i * SW + kk);
            #pragma unroll
            for (int j = 0; j < 4; j++) bq[j] = *(const float4*)(up + j * SU + kk);
            #pragma unroll
            for (int i = 0; i < 4; i++) {
                #pragma unroll
                for (int j = 0; j < 4; j++) {
                    acc[i][j] += aq[i].x * bq[j].x;
                    acc[i][j] += aq[i].y * bq[j].y;
                    acc[i][j] += aq[i].z * bq[j].z;
                    acc[i][j] += aq[i].w * bq[j].w;
                }
            }
        }
        float* pg = part + g * 1152;
        #pragma unroll
        for (int i = 0; i < 4; i++)
            #pragma unroll
            for (int j = 0; j < 4; j++)
                pg[(o0 + j) * 32 + (t0 + i)] = acc[i][j];
    }
    __syncthreads();

    // ---- prefetch o tile into u_s region (stride 512), overlapped with reduce/softmax ----
    for (int i = tid; i < TO * DD / 4; i += 512) {
        int r = i >> 7, k4 = i & 127;
        cpa16(&u_s[r * DD + k4 * 4], og + r * DD + k4 * 4);
    }
    cp_commit();

    // ---- reduce K-split partials, scale by 1/sqrt(D) ----
    const float scale = 0.044194173824159216f;  // 1/sqrt(512)
    float red[3];
    #pragma unroll
    for (int m = 0; m < 3; m++) {
        int idx = tid + m * 512;
        if (idx < 1152)
            red[m] = (part[idx] + part[1152 + idx] + part[2304 + idx] + part[3456 + idx]) * scale;
    }
    __syncthreads();
    #pragma unroll
    for (int m = 0; m < 3; m++) {
        int idx = tid + m * 512;
        if (idx < 1152) {
            int o = idx >> 5, t = idx & 31;
            att_ts[o * 36 + t] = red[m];
        }
    }
    __syncthreads();

    // ---- softmax over To per t-row; each warp handles t = warp and warp+16 ----
    #pragma unroll
    for (int rr = 0; rr < 2; rr++) {
        const int t = warp + rr * 16;
        float v0 = att_ts[lane * 36 + t];
        float v1 = (lane < 4) ? att_ts[(32 + lane) * 36 + t] : -3.4e38f;
        float mx = fmaxf(v0, v1);
        #pragma unroll
        for (int off = 16; off; off >>= 1) mx = fmaxf(mx, __shfl_xor_sync(0xffffffffu, mx, off));
        float e0 = __expf(v0 - mx);
        float e1 = (lane < 4) ? __expf(v1 - mx) : 0.f;
        float s = e0 + e1;
        #pragma unroll
        for (int off = 16; off; off >>= 1) s += __shfl_xor_sync(0xffffffffu, s, off);
        float rs = __frcp_rn(s);
        float p0 = e0 * rs;
        att_ts[lane * 36 + t] = p0;
        float* ao = att_out + ((size_t)((wb * BO + b) * TW + t)) * TO;
        ao[lane] = p0;
        if (lane < 4) {
            float p1 = e1 * rs;
            att_ts[(32 + lane) * 36 + t] = p1;
            ao[32 + lane] = p1;
        }
    }
    cp_wait0();
    __syncthreads();

    // ---- stage 2: att_V_o(32x512) = att(32x36) . o(36x512); fused logits dot ----
    const int tr2 = tid >> 6;      // 0..7
    const int dc  = tid & 63;      // 0..63
    const int t0  = tr2 * 4;
    float acc2[4][8];
    #pragma unroll
    for (int i = 0; i < 4; i++)
        #pragma unroll
        for (int j = 0; j < 8; j++) acc2[i][j] = 0.f;

    const float* osb = u_s;  // o tile [36][512]
    #pragma unroll 4
    for (int o = 0; o < 36; o++) {
        float4 a  = *(const float4*)&att_ts[o * 36 + t0];
        float4 bA = *(const float4*)&osb[o * DD + dc * 4];
        float4 bB = *(const float4*)&osb[o * DD + 256 + dc * 4];
        float av[4] = {a.x, a.y, a.z, a.w};
        #pragma unroll
        for (int i = 0; i < 4; i++) {
            acc2[i][0] += av[i] * bA.x;
            acc2[i][1] += av[i] * bA.y;
            acc2[i][2] += av[i] * bA.z;
            acc2[i][3] += av[i] * bA.w;
            acc2[i][4] += av[i] * bB.x;
            acc2[i][5] += av[i] * bB.y;
            acc2[i][6] += av[i] * bB.z;
            acc2[i][7] += av[i] * bB.w;
        }
    }

    // ---- write att_V_o (scalar stores: output region is 4B-aligned only) + logits ----
    float* avo = avo_out + ((size_t)((wb * BO + b) * TW + t0)) * DD;
    #pragma unroll
    for (int i = 0; i < 4; i++) {
        float* row = avo + (size_t)i * DD;
        row[dc * 4 + 0] = acc2[i][0];
        row[dc * 4 + 1] = acc2[i][1];
        row[dc * 4 + 2] = acc2[i][2];
        row[dc * 4 + 3] = acc2[i][3];
        row[256 + dc * 4 + 0] = acc2[i][4];
        row[256 + dc * 4 + 1] = acc2[i][5];
        row[256 + dc * 4 + 2] = acc2[i][6];
        row[256 + dc * 4 + 3] = acc2[i][7];

        float4 wa  = *(const float4*)&w_s[(t0 + i) * SW + dc * 4];
        float4 wbv = *(const float4*)&w_s[(t0 + i) * SW + 256 + dc * 4];
        float l = acc2[i][0] * wa.x  + acc2[i][1] * wa.y  + acc2[i][2] * wa.z  + acc2[i][3] * wa.w
                + acc2[i][4] * wbv.x + acc2[i][5] * wbv.y + acc2[i][6] * wbv.z + acc2[i][7] * wbv.w;
        #pragma unroll
        for (int off = 16; off; off >>= 1) l += __shfl_xor_sync(0xffffffffu, l, off);
        if (lane == 0) lp[(warp & 1) * 32 + (t0 + i)] = l;   // deterministic 2-partial split
    }
    __syncthreads();
    if (tid < 32)
        g_logits[((size_t)wb * TW + tid) * BO + b] = lp[tid] + lp[32 + tid];
}

// ---- loss: log_softmax over Bo, masked mean over t, -mean(diag) ----
__global__ void cap_loss(const int* __restrict__ mask, float* __restrict__ out)
{
    __shared__ float warr[32];
    const int tid = threadIdx.x, warp = tid >> 5, lane = tid & 31;
    float wtotal = 0.f;
    #pragma unroll
    for (int h = 0; h < 2; h++) {
        const int w = warp * 2 + h;
        const float* lw = g_logits + (size_t)w * TW * BO;
        float acc = 0.f, cnt = 0.f;
        for (int t = 0; t < TW; t++) {
            float v0 = lw[t * BO + lane];
            float v1 = lw[t * BO + lane + 32];
            float mx = fmaxf(v0, v1);
            #pragma unroll
            for (int off = 16; off; off >>= 1) mx = fmaxf(mx, __shfl_xor_sync(0xffffffffu, mx, off));
            float s = expf(v0 - mx) + expf(v1 - mx);
            #pragma unroll
            for (int off = 16; off; off >>= 1) s += __shfl_xor_sync(0xffffffffu, s, off);
            float lse = mx + logf(s);
            float diag = lw[t * BO + w];
            if (mask[w * TW + t] == 0) { acc += diag - lse; cnt += 1.f; }
        }
        wtotal += acc * (1.f / (cnt + 1e-6f));
    }
    if (lane == 0) warr[warp] = wtotal;
    __syncthreads();
    if (tid == 0) {
        float s = 0.f;
        for (int i = 0; i < 32; i++) s += warr[i];
        out[0] = -s * (1.0f / 64.0f);
    }
}

extern "C" void kernel_launch(void* const* d_in, const int* in_sizes, int n_in,
                              void* d_out, int out_size)
{
    (void)in_sizes; (void)n_in; (void)out_size;
    const float* o_g  = (const float*)d_in[0];
    const float* u_g  = (const float*)d_in[1];
    const float* w_g  = (const float*)d_in[2];
    const int*   mask = (const int*)d_in[3];
    float* out = (float*)d_out;

    cudaFuncSetAttribute(cap_main, cudaFuncAttributeMaxDynamicSharedMemorySize, SMEM_BYTES);

    // output layout: [0]=loss, [1 .. ) att (Bw,Bo,Tw,To), then att_V_o (Bw,Bo,Tw,D)
    float* att_out = out + 1;
    float* avo_out = out + 1 + (size_t)BW * BO * TW * TO;

    dim3 grid(BO, BW);
    cap_main<<<grid, 512, SMEM_BYTES>>>(o_g, u_g, w_g, att_out, avo_out);
    cap_loss<<<1, 1024>>>(mask, out);
}

// round 7
// speedup vs baseline: 1.1008x; 1.1008x over previous
#include <cuda_runtime.h>
#include <cuda_bf16.h>
#include <cstdint>
#include <cstddef>

// Shapes (fixed)
#define BW 64
#define BO 64
#define TW 32
#define TO 36
#define DD 512
#define NTILE (BW * BO)

// smem row stride for w/u tiles (floats): 512 + 4 pad (bank spread, 16B aligned)
#define SW 516

// dynamic smem layout (float offsets). Last row of each padded tile is
// truncated to 512 (pad after final row never read).
#define OFF_U 16508                    // w: 31*516+512 = 16508 floats
#define OFF_O (OFF_U + 18572)          // u: 35*516+512 = 18572 -> 35080
#define OFF_PART (OFF_O + 18432)       // o: 36*512 = 18432 -> 53512
#define SMEM_FLOATS (OFF_PART + 3456)  // part: 3*1152 (groups 1..3)
#define SMEM_BYTES (SMEM_FLOATS * 4)   // 227,872 B <= 232,448 limit

// scratch
__device__ float g_logits[BW * TW * BO];  // [w][t][b]
__device__ float g_wloss[BW];

__device__ __forceinline__ void cpa16(float* s, const float* g) {
    uint32_t sa = (uint32_t)__cvta_generic_to_shared(s);
    asm volatile("cp.async.cg.shared.global [%0], [%1], 16;" :: "r"(sa), "l"(g));
}
__device__ __forceinline__ void cp_commit() { asm volatile("cp.async.commit_group;"); }
__device__ __forceinline__ void cp_wait0()  { asm volatile("cp.async.wait_group 0;"); }
__device__ __forceinline__ void cp_wait1()  { asm volatile("cp.async.wait_group 1;"); }

__global__ void __launch_bounds__(512, 1)
cap_main(const float* __restrict__ o_g, const float* __restrict__ u_g,
         const float* __restrict__ w_g,
         float* __restrict__ att_out, float* __restrict__ avo_out)
{
    extern __shared__ float sm[];
    float* w_s    = sm;                 // [32][516] (last row 512)
    float* u_s    = sm + OFF_U;         // [36][516] (last row 512)
    float* o_s    = sm + OFF_O;         // [36][512]
    float* part   = sm + OFF_PART;      // [3][36][32] k-split partials (groups 1..3)
    float* att_ts = part;               // [36][36] overlays part (read-all -> sync -> write)
    float* lp     = part + 1296;        // [2][32] logits partials (disjoint from att_ts)

    const int tid  = threadIdx.x;
    const int lane = tid & 31;
    const int warp = tid >> 5;

    // static tile range for this block (tiles ordered wb-major -> w reuse)
    const int nblk  = gridDim.x;
    const int r     = blockIdx.x;
    const int bas   = NTILE / nblk, rem = NTILE % nblk;
    const int cnt   = bas + (r < rem ? 1 : 0);
    const int start = r * bas + (r < rem ? r : rem);

    // ---- prologue: load w(wb0) and u(b0) ----
    {
        const int tile0 = start;
        const int wb0 = tile0 >> 6, b0 = tile0 & 63;
        const float* wg = w_g + (size_t)wb0 * TW * DD;
        const float* ug = u_g + (size_t)b0 * TO * DD;
        for (int i = tid; i < TW * DD / 4; i += 512) {
            int t = i >> 7, k4 = i & 127;
            cpa16(&w_s[t * SW + k4 * 4], wg + t * DD + k4 * 4);
        }
        for (int i = tid; i < TO * DD / 4; i += 512) {
            int t = i >> 7, k4 = i & 127;
            cpa16(&u_s[t * SW + k4 * 4], ug + t * DD + k4 * 4);
        }
        cp_commit(); cp_wait0(); __syncthreads();
    }

    for (int it = 0; it < cnt; ++it) {
        const int tile = start + it;
        const int wb = tile >> 6, b = tile & 63;

        if (it) { cp_wait0(); __syncthreads(); }   // u (+w) prefetch landed

        // ---- (A) prefetch o(b) into o_s (overlaps stage 1) ----
        {
            const float* og = o_g + (size_t)b * TO * DD;
            for (int i = tid; i < TO * DD / 4; i += 512) {
                int t = i >> 7, k4 = i & 127;
                cpa16(&o_s[t * DD + k4 * 4], og + t * DD + k4 * 4);
            }
            cp_commit();                            // group O
        }

        // ---- stage 1: scores(32x36) = w . u^T, 4-way K-split, 4x4 tiles ----
        float s1acc[4][4];
        int t0a = 0, o0a = 0;
        if (tid < 288) {
            const int g    = tid / 72;
            const int id72 = tid % 72;
            const int oc   = id72 >> 3;
            const int tr   = id72 & 7;
            t0a = tr * 4; o0a = oc * 4;
            const float* wp = w_s + t0a * SW + g * 128;
            const float* up = u_s + o0a * SW + g * 128;

            #pragma unroll
            for (int i = 0; i < 4; i++)
                #pragma unroll
                for (int j = 0; j < 4; j++) s1acc[i][j] = 0.f;

            #pragma unroll 2
            for (int k4 = 0; k4 < 32; k4++) {
                const int kk = k4 * 4;
                float4 aq[4], bq[4];
                #pragma unroll
                for (int i = 0; i < 4; i++) aq[i] = *(const float4*)(wp + i * SW + kk);
                #pragma unroll
                for (int j = 0; j < 4; j++) bq[j] = *(const float4*)(up + j * SW + kk);
                #pragma unroll
                for (int i = 0; i < 4; i++) {
                    #pragma unroll
                    for (int j = 0; j < 4; j++) {
                        s1acc[i][j] += aq[i].x * bq[j].x;
                        s1acc[i][j] += aq[i].y * bq[j].y;
                        s1acc[i][j] += aq[i].z * bq[j].z;
                        s1acc[i][j] += aq[i].w * bq[j].w;
                    }
                }
            }
            if (g) {  // groups 1..3 spill partials; group 0 keeps registers
                float* pg = part + (g - 1) * 1152;
                #pragma unroll
                for (int i = 0; i < 4; i++)
                    #pragma unroll
                    for (int j = 0; j < 4; j++)
                        pg[(o0a + j) * 32 + (t0a + i)] = s1acc[i][j];
            }
        }
        __syncthreads();

        // ---- (D) prefetch u(next) into u_s (u consumed by stage 1) ----
        {
            const int ntile = (it + 1 < cnt) ? tile + 1 : tile;  // clamp: dummy reload on last
            const int nb = ntile & 63;
            const float* ug = u_g + (size_t)nb * TO * DD;
            for (int i = tid; i < TO * DD / 4; i += 512) {
                int t = i >> 7, k4 = i & 127;
                cpa16(&u_s[t * SW + k4 * 4], ug + t * DD + k4 * 4);
            }
            cp_commit();                            // group U
        }

        // ---- reduce K-split partials into group-0 registers, scale ----
        const float scale = 0.044194173824159216f;  // 1/sqrt(512)
        if (tid < 72) {
            #pragma unroll
            for (int i = 0; i < 4; i++)
                #pragma unroll
                for (int j = 0; j < 4; j++) {
                    const int idx = (o0a + j) * 32 + (t0a + i);
                    s1acc[i][j] = (s1acc[i][j] + part[idx] + part[1152 + idx]
                                   + part[2304 + idx]) * scale;
                }
        }
        __syncthreads();                            // all partial reads done
        if (tid < 72) {                             // write scores o-major [o][t] (overlays part)
            #pragma unroll
            for (int i = 0; i < 4; i++)
                #pragma unroll
                for (int j = 0; j < 4; j++)
                    att_ts[(o0a + j) * 36 + (t0a + i)] = s1acc[i][j];
        }
        __syncthreads();

        // ---- softmax over To; warp handles t = warp and warp+16 ----
        #pragma unroll
        for (int rr = 0; rr < 2; rr++) {
            const int t = warp + rr * 16;
            float v0 = att_ts[lane * 36 + t];
            float v1 = (lane < 4) ? att_ts[(32 + lane) * 36 + t] : -3.4e38f;
            float mx = fmaxf(v0, v1);
            #pragma unroll
            for (int off = 16; off; off >>= 1) mx = fmaxf(mx, __shfl_xor_sync(0xffffffffu, mx, off));
            float e0 = __expf(v0 - mx);
            float e1 = (lane < 4) ? __expf(v1 - mx) : 0.f;
            float s = e0 + e1;
            #pragma unroll
            for (int off = 16; off; off >>= 1) s += __shfl_xor_sync(0xffffffffu, s, off);
            float rs = __frcp_rn(s);
            float p0 = e0 * rs;
            att_ts[lane * 36 + t] = p0;
            float* ao = att_out + ((size_t)((wb * BO + b) * TW + t)) * TO;
            ao[lane] = p0;
            if (lane < 4) {
                float p1 = e1 * rs;
                att_ts[(32 + lane) * 36 + t] = p1;
                ao[32 + lane] = p1;
            }
        }
        cp_wait1();                                 // group O done (U may still fly)
        __syncthreads();

        // ---- stage 2: att_V_o(32x512) = att(32x36) . o(36x512); fused logits ----
        const int tr2 = tid >> 6;
        const int dc  = tid & 63;
        const int t0  = tr2 * 4;
        float acc2[4][8];
        #pragma unroll
        for (int i = 0; i < 4; i++)
            #pragma unroll
            for (int j = 0; j < 8; j++) acc2[i][j] = 0.f;

        #pragma unroll 4
        for (int o = 0; o < 36; o++) {
            float4 a  = *(const float4*)&att_ts[o * 36 + t0];
            float4 bA = *(const float4*)&o_s[o * DD + dc * 4];
            float4 bB = *(const float4*)&o_s[o * DD + 256 + dc * 4];
            float av[4] = {a.x, a.y, a.z, a.w};
            #pragma unroll
            for (int i = 0; i < 4; i++) {
                acc2[i][0] += av[i] * bA.x;
                acc2[i][1] += av[i] * bA.y;
                acc2[i][2] += av[i] * bA.z;
                acc2[i][3] += av[i] * bA.w;
                acc2[i][4] += av[i] * bB.x;
                acc2[i][5] += av[i] * bB.y;
                acc2[i][6] += av[i] * bB.z;
                acc2[i][7] += av[i] * bB.w;
            }
        }

        float* avo = avo_out + ((size_t)((wb * BO + b) * TW + t0)) * DD;
        #pragma unroll
        for (int i = 0; i < 4; i++) {
            float* row = avo + (size_t)i * DD;
            row[dc * 4 + 0] = acc2[i][0];
            row[dc * 4 + 1] = acc2[i][1];
            row[dc * 4 + 2] = acc2[i][2];
            row[dc * 4 + 3] = acc2[i][3];
            row[256 + dc * 4 + 0] = acc2[i][4];
            row[256 + dc * 4 + 1] = acc2[i][5];
            row[256 + dc * 4 + 2] = acc2[i][6];
            row[256 + dc * 4 + 3] = acc2[i][7];

            float4 wa  = *(const float4*)&w_s[(t0 + i) * SW + dc * 4];
            float4 wbv = *(const float4*)&w_s[(t0 + i) * SW + 256 + dc * 4];
            float l = acc2[i][0] * wa.x  + acc2[i][1] * wa.y  + acc2[i][2] * wa.z  + acc2[i][3] * wa.w
                    + acc2[i][4] * wbv.x + acc2[i][5] * wbv.y + acc2[i][6] * wbv.z + acc2[i][7] * wbv.w;
            #pragma unroll
            for (int off = 16; off; off >>= 1) l += __shfl_xor_sync(0xffffffffu, l, off);
            if (lane == 0) lp[(warp & 1) * 32 + (t0 + i)] = l;
        }
        __syncthreads();
        if (tid < 32)
            g_logits[((size_t)wb * TW + tid) * BO + b] = lp[tid] + lp[32 + tid];

        // ---- (H) prefetch w if wb changes (w_s reads finished above) ----
        if (it + 1 < cnt) {
            const int nwb = (tile + 1) >> 6;
            if (nwb != wb) {
                const float* wg = w_g + (size_t)nwb * TW * DD;
                for (int i = tid; i < TW * DD / 4; i += 512) {
                    int t = i >> 7, k4 = i & 127;
                    cpa16(&w_s[t * SW + k4 * 4], wg + t * DD + k4 * 4);
                }
                cp_commit();                        // group W
            }
        }
    }
    cp_wait0();   // drain outstanding prefetches before exit
}

// ---- loss, stage 1: per-w masked mean of (diag - lse) -> g_wloss[w] ----
__global__ void cap_loss1(const int* __restrict__ mask)
{
    __shared__ float sacc[8], scnt[8];
    const int w = blockIdx.x;
    const int tid = threadIdx.x, warp = tid >> 5, lane = tid & 31;
    const float* lw = g_logits + (size_t)w * TW * BO;
    float acc = 0.f, cntv = 0.f;
    for (int t = warp; t < TW; t += 8) {
        float v0 = lw[t * BO + lane];
        float v1 = lw[t * BO + 32 + lane];
        float mx = fmaxf(v0, v1);
        #pragma unroll
        for (int off = 16; off; off >>= 1) mx = fmaxf(mx, __shfl_xor_sync(0xffffffffu, mx, off));
        float s = expf(v0 - mx) + expf(v1 - mx);
        #pragma unroll
        for (int off = 16; off; off >>= 1) s += __shfl_xor_sync(0xffffffffu, s, off);
        if (lane == 0 && mask[w * TW + t] == 0) {
            acc += lw[t * BO + w] - (mx + logf(s));
            cntv += 1.f;
        }
    }
    if (lane == 0) { sacc[warp] = acc; scnt[warp] = cntv; }
    __syncthreads();
    if (tid == 0) {
        float a = 0.f, c = 0.f;
        #pragma unroll
        for (int i = 0; i < 8; i++) { a += sacc[i]; c += scnt[i]; }
        g_wloss[w] = a / (c + 1e-6f);
    }
}

// ---- loss, stage 2: -mean over w ----
__global__ void cap_loss2(float* __restrict__ out)
{
    __shared__ float sh[2];
    const int tid = threadIdx.x, lane = tid & 31, warp = tid >> 5;
    float v = g_wloss[tid];
    #pragma unroll
    for (int off = 16; off; off >>= 1) v += __shfl_xor_sync(0xffffffffu, v, off);
    if (lane == 0) sh[warp] = v;
    __syncthreads();
    if (tid == 0) out[0] = -(sh[0] + sh[1]) * (1.0f / 64.0f);
}

extern "C" void kernel_launch(void* const* d_in, const int* in_sizes, int n_in,
                              void* d_out, int out_size)
{
    (void)in_sizes; (void)n_in; (void)out_size;
    const float* o_g  = (const float*)d_in[0];
    const float* u_g  = (const float*)d_in[1];
    const float* w_g  = (const float*)d_in[2];
    const int*   mask = (const int*)d_in[3];
    float* out = (float*)d_out;

    static int nsm = 0;
    if (nsm == 0) {
        int dev = 0;
        cudaGetDevice(&dev);
        cudaDeviceGetAttribute(&nsm, cudaDevAttrMultiProcessorCount, dev);
        if (nsm <= 0) nsm = 148;
        cudaFuncSetAttribute(cap_main, cudaFuncAttributeMaxDynamicSharedMemorySize, SMEM_BYTES);
    }

    // output layout: [0]=loss, att (Bw,Bo,Tw,To), att_V_o (Bw,Bo,Tw,D)
    float* att_out = out + 1;
    float* avo_out = out + 1 + (size_t)BW * BO * TW * TO;

    cap_main<<<nsm, 512, SMEM_BYTES>>>(o_g, u_g, w_g, att_out, avo_out);
    cap_loss1<<<64, 256>>>(mask);
    cap_loss2<<<1, 64>>>(out);
}